// round 9
// baseline (speedup 1.0000x reference)
#include <cuda_runtime.h>
#include <stdint.h>

#define NN    20000
#define EE    200000
#define PP    300
#define EPE   2000
#define KKEEP 16000
#define HS    4096
#define HM    4095
#define NB    8192      // bins per histogram copy
#define NT    1024
#define GRID  296

// dynamic smem layout (bytes):
//   ukey : 20000 u32        [0,      80000)
//   keysh: 4096  int        [80000,  96384)
//   val  : 4096  int        [96384, 112768)
//   mv   : 2048  float4     [112768,145536)
//   hist : 2*8192 u32       [145536,211072)   (also klist / dl scratch)
#define SMEM_BYTES 211072

__device__ float4 g_h4[NN];
__device__ float  g_hp[NN * 3];
__device__ float  g_agg[NN * 3];
__device__ float  g_pathC[PP];

typedef unsigned long long u64t;
__device__ __forceinline__ u64t pk2(float a, float b) {
    u64t r; asm("mov.b64 %0,{%1,%2};" : "=l"(r) : "f"(a), "f"(b)); return r;
}
__device__ __forceinline__ float2 upk2(u64t v) {
    float2 f; asm("mov.b64 {%0,%1},%2;" : "=f"(f.x), "=f"(f.y) : "l"(v)); return f;
}
__device__ __forceinline__ u64t fma2(u64t a, u64t b, u64t c) {
    u64t r; asm("fma.rn.f32x2 %0,%1,%2,%3;" : "=l"(r) : "l"(a), "l"(b), "l"(c)); return r;
}

__device__ __forceinline__ unsigned fkey(float f) {
    unsigned u = __float_as_uint(f);
    return (u & 0x80000000u) ? ~u : (u | 0x80000000u);
}

__device__ __forceinline__ float tanh_fast(float x) {
    float a = fabsf(x);
    if (a < 0.53f) {
        float x2 = x * x;
        float p = fmaf(x2, -5.3968254e-2f, 1.3333333e-1f);
        p = fmaf(x2, p, -3.3333333e-1f);
        p = fmaf(x2, p, 1.0f);
        return x * p;
    }
    return tanhf(x);
}
__device__ __forceinline__ float exp_fast(float t) {
    if (fabsf(t) < 0.3f) {
        float p = fmaf(t, 4.1666668e-2f, 1.6666667e-1f);
        p = fmaf(t, p, 0.5f);
        p = fmaf(t, p, 1.0f);
        p = fmaf(t, p, 1.0f);
        return p;
    }
    return __expf(t);
}

__device__ __forceinline__ void node_val(
    float4 hv, float m0, float m1, float m2, float ar,
    const float* Wl, const float* Wr,
    float bl0, float bl1, float bl2,
    float wo0, float wo1, float wo2, float pb,
    float gW0, float gW1, float gW2,
    unsigned& u, float& e, float& k0, float& k1, float& k2)
{
    float t0 = fmaf(hv.x, Wr[0], fmaf(hv.y, Wr[3], fmaf(hv.z, Wr[6], bl0)));
    float t1 = fmaf(hv.x, Wr[1], fmaf(hv.y, Wr[4], fmaf(hv.z, Wr[7], bl1)));
    float t2 = fmaf(hv.x, Wr[2], fmaf(hv.y, Wr[5], fmaf(hv.z, Wr[8], bl2)));
    float xc0 = fmaxf(fmaf(m0, Wl[0], fmaf(m1, Wl[3], fmaf(m2, Wl[6], t0))), 0.f);
    float xc1 = fmaxf(fmaf(m0, Wl[1], fmaf(m1, Wl[4], fmaf(m2, Wl[7], t1))), 0.f);
    float xc2 = fmaxf(fmaf(m0, Wl[2], fmaf(m1, Wl[5], fmaf(m2, Wl[8], t2))), 0.f);
    float sc = fmaf(xc0, wo0, fmaf(xc1, wo1, fmaf(xc2, wo2, pb + ar)));
    u = fkey(sc);
    float tv = tanh_fast(sc);
    k0 = xc0 * tv; k1 = xc1 * tv; k2 = xc2 * tv;
    float l = fmaf(k0, gW0, fmaf(k1, gW1, k2 * gW2));
    e = exp_fast(l);
}

// tail after the relu'd xc (shared by packed path)
__device__ __forceinline__ void node_tail(
    float xc0, float xc1, float xc2,
    float wo0, float wo1, float wo2, float pb,
    float gW0, float gW1, float gW2,
    unsigned& u, float& e, float& k0, float& k1, float& k2)
{
    float sc = fmaf(xc0, wo0, fmaf(xc1, wo1, fmaf(xc2, wo2, pb + 0.f)));
    u = fkey(sc);
    float tv = tanh_fast(sc);
    k0 = xc0 * tv; k1 = xc1 * tv; k2 = xc2 * tv;
    float l = fmaf(k0, gW0, fmaf(k1, gW1, k2 * gW2));
    e = exp_fast(l);
}

// ---------------- global stage ----------------
__global__ void k_hp(const float* __restrict__ x, const float* __restrict__ Wp,
                     const float* __restrict__ bp) {
    int i = blockIdx.x * blockDim.x + threadIdx.x;
    if (i >= NN) return;
    float x0 = x[3*i], x1 = x[3*i+1], x2 = x[3*i+2];
#pragma unroll
    for (int c = 0; c < 3; c++) {
        float v = fmaxf(bp[c] + x0*Wp[c] + x1*Wp[3+c] + x2*Wp[6+c], 0.f);
        g_hp[3*i+c] = v;
        g_agg[3*i+c] = v;
    }
}

__global__ void k_segmax(const int* __restrict__ ei) {
    int e = blockIdx.x * blockDim.x + threadIdx.x;
    if (e >= EE) return;
    int s = ei[e], d = ei[EE + e];
#pragma unroll
    for (int c = 0; c < 3; c++)
        atomicMax((int*)&g_agg[3*d+c], __float_as_int(g_hp[3*s+c]));
}

__global__ void k_h(const float* __restrict__ x, const float* __restrict__ Ws,
                    const float* __restrict__ Wn, const float* __restrict__ bc) {
    int i = blockIdx.x * blockDim.x + threadIdx.x;
    if (i >= NN) return;
    float x0 = x[3*i], x1 = x[3*i+1], x2 = x[3*i+2];
    float a0 = g_agg[3*i], a1 = g_agg[3*i+1], a2 = g_agg[3*i+2];
    float4 o;
    o.x = tanhf(bc[0] + x0*Ws[0] + x1*Ws[3] + x2*Ws[6] + a0*Wn[0] + a1*Wn[3] + a2*Wn[6]);
    o.y = tanhf(bc[1] + x0*Ws[1] + x1*Ws[4] + x2*Ws[7] + a0*Wn[1] + a1*Wn[4] + a2*Wn[7]);
    o.z = tanhf(bc[2] + x0*Ws[2] + x1*Ws[5] + x2*Ws[8] + a0*Wn[2] + a1*Wn[5] + a2*Wn[8]);
    o.w = 0.f;
    g_h4[i] = o;
}

// ---------------- fully fused per-pathway kernel ----------------
__global__ void __launch_bounds__(NT, 1) k_path(
    const int*   __restrict__ pe,
    const float* __restrict__ subWl, const float* __restrict__ subbl,
    const float* __restrict__ subWr,
    const float* __restrict__ pWrel, const float* __restrict__ pWroot,
    const float* __restrict__ poolb,
    const float* __restrict__ gateW, const float* __restrict__ gateb,
    const float* __restrict__ linW,  const float* __restrict__ linb,
    const float* __restrict__ mlpW)
{
    extern __shared__ char sm[];
    unsigned* ukey  = (unsigned*)(sm);
    int*      keysh = (int*)     (sm + 80000);
    int*      val   = (int*)     (sm + 96384);
    float4*   mv    = (float4*)  (sm + 112768);
    unsigned* hist  = (unsigned*)(sm + 145536);

    __shared__ unsigned s_wa[32], s_wb[32];
    __shared__ unsigned s_bin, s_rem, s_cnt, s_itie, s_dn, s_tot;
    __shared__ float    fred[128];

    const int tid  = threadIdx.x;
    const int lane = tid & 31;
    const int wid  = tid >> 5;

#pragma unroll 1
    for (int rep = 0; rep < 2; rep++) {
        const int p = blockIdx.x + rep * GRID;
        if (p >= PP) break;

        float Wl[9], Wr[9];
#pragma unroll
        for (int q = 0; q < 9; q++) { Wl[q] = __ldg(subWl + 9*p + q); Wr[q] = __ldg(subWr + 9*p + q); }
        const float bl0 = __ldg(subbl+3*p), bl1 = __ldg(subbl+3*p+1), bl2 = __ldg(subbl+3*p+2);
        const float wr0 = __ldg(pWrel+3*p), wr1 = __ldg(pWrel+3*p+1), wr2 = __ldg(pWrel+3*p+2);
        const float wo0 = __ldg(pWroot+3*p), wo1 = __ldg(pWroot+3*p+1), wo2 = __ldg(pWroot+3*p+2);
        const float pb  = __ldg(poolb + p);
        const float gW0 = __ldg(gateW+3*p), gW1 = __ldg(gateW+3*p+1), gW2 = __ldg(gateW+3*p+2);

        // ---- phase 0 ----
        ((int4*)keysh)[tid] = make_int4(0, 0, 0, 0);
        float4 z4 = make_float4(0.f, 0.f, 0.f, 0.f);
        mv[tid] = z4; mv[tid + NT] = z4;
        __syncthreads();

        const int* ps = pe + p * 2 * EPE;
        const int* pd = ps + EPE;
        const int e0 = tid, e1 = tid + NT;
        int slotA = -1, slotB = -1;

        // ---- phase 1a ----
        if (e0 < EPE) {
            int d = pd[e0];
            unsigned slot = ((unsigned)d * 2654435761u) >> 20;
            for (;;) {
                int prev = atomicCAS(&keysh[slot], 0, d + 1);
                if (prev == 0 || prev == d + 1) break;
                slot = (slot + 1) & HM;
            }
            slotA = (int)slot;
        }
        if (e1 < EPE) {
            int d = pd[e1];
            unsigned slot = ((unsigned)d * 2654435761u) >> 20;
            for (;;) {
                int prev = atomicCAS(&keysh[slot], 0, d + 1);
                if (prev == 0 || prev == d + 1) break;
                slot = (slot + 1) & HM;
            }
            slotB = (int)slot;
        }
        __syncthreads();

        // ---- phase 1b: compaction + klist (hist region reused as klist) ----
        int* klist = (int*)hist;
        {
            int4 kk = ((int4*)keysh)[tid];
            unsigned c = (kk.x != 0) + (kk.y != 0) + (kk.z != 0) + (kk.w != 0);
            unsigned v = c;
#pragma unroll
            for (int d = 1; d < 32; d <<= 1) { unsigned t = __shfl_up_sync(~0u, v, d); if (lane >= d) v += t; }
            if (lane == 31) s_wa[wid] = v;
            __syncthreads();
            if (wid == 0) {
                unsigned x = s_wa[lane];
#pragma unroll
                for (int d = 1; d < 32; d <<= 1) { unsigned t = __shfl_up_sync(~0u, x, d); if (lane >= d) x += t; }
                s_wb[lane] = x;
            }
            __syncthreads();
            unsigned excl = (v - c) + ((wid > 0) ? s_wb[wid - 1] : 0u);
            int b = (int)excl;
            if (kk.x) { val[4*tid]   = b; klist[b] = kk.x - 1; b++; }
            if (kk.y) { val[4*tid+1] = b; klist[b] = kk.y - 1; b++; }
            if (kk.z) { val[4*tid+2] = b; klist[b] = kk.z - 1; b++; }
            if (kk.w) { val[4*tid+3] = b; klist[b] = kk.w - 1; b++; }
            if (tid == NT - 1) s_tot = excl + c;
        }
        __syncthreads();

        // ---- phase 1c ----
        float* mvf = (float*)mv;
        int idxA = (slotA >= 0) ? val[slotA] : -1;
        int idxB = (slotB >= 0) ? val[slotB] : -1;
        if (e0 < EPE) {
            float4 hv = g_h4[ps[e0]];
            atomicAdd(&mvf[4*idxA],   hv.x);
            atomicAdd(&mvf[4*idxA+1], hv.y);
            atomicAdd(&mvf[4*idxA+2], hv.z);
            atomicAdd(&mvf[4*idxA+3], 1.f);
        }
        if (e1 < EPE) {
            float4 hv = g_h4[ps[e1]];
            atomicAdd(&mvf[4*idxB],   hv.x);
            atomicAdd(&mvf[4*idxB+1], hv.y);
            atomicAdd(&mvf[4*idxB+2], hv.z);
            atomicAdd(&mvf[4*idxB+3], 1.f);
        }
        __syncthreads();

        // ---- phase 1d ----
        {
            int tot = (int)s_tot;
            for (int idx = tid; idx < tot; idx += NT) {
                float4 v = mv[idx];
                float inv = 1.f / v.w;
                mv[idx] = make_float4(v.x * inv, v.y * inv, v.z * inv, 0.f);
            }
        }
        __syncthreads();

        // ---- phase 2 ----
#pragma unroll
        for (int ee = 0; ee < 2; ee++) {
            int e = (ee == 0) ? e0 : e1;
            int myidx = (ee == 0) ? idxA : idxB;
            if (e < EPE) {
                int s = ps[e];
                float4 hv = g_h4[s];
                float m0 = 0.f, m1 = 0.f, m2 = 0.f;
                unsigned slot = ((unsigned)s * 2654435761u) >> 20;
                int want = s + 1;
                for (;;) {
                    int k2 = keysh[slot];
                    if (k2 == want) { float4 mm = mv[val[slot]]; m0 = mm.x; m1 = mm.y; m2 = mm.z; break; }
                    if (k2 == 0) break;
                    slot = (slot + 1) & HM;
                }
                float xc0 = fmaxf(fmaf(m0, Wl[0], fmaf(m1, Wl[3], fmaf(m2, Wl[6], fmaf(hv.x, Wr[0], fmaf(hv.y, Wr[3], fmaf(hv.z, Wr[6], bl0)))))), 0.f);
                float xc1 = fmaxf(fmaf(m0, Wl[1], fmaf(m1, Wl[4], fmaf(m2, Wl[7], fmaf(hv.x, Wr[1], fmaf(hv.y, Wr[4], fmaf(hv.z, Wr[7], bl1)))))), 0.f);
                float xc2 = fmaxf(fmaf(m0, Wl[2], fmaf(m1, Wl[5], fmaf(m2, Wl[8], fmaf(hv.x, Wr[2], fmaf(hv.y, Wr[5], fmaf(hv.z, Wr[8], bl2)))))), 0.f);
                float vv = fmaf(xc0, wr0, fmaf(xc1, wr1, xc2 * wr2));
                atomicAdd(&mvf[4*myidx+3], vv);
            }
        }
        __syncthreads();

        // ---- phase 3: packed f32x2, 2 nodes/thread ----
        float ssum = 0.f, a0 = 0.f, a1 = 0.f, a2 = 0.f;
        unsigned mymin = 0xffffffffu, mymax = 0u;
        {
            u64t w0 = pk2(Wr[0], Wr[0]), w1 = pk2(Wr[1], Wr[1]), w2 = pk2(Wr[2], Wr[2]);
            u64t w3 = pk2(Wr[3], Wr[3]), w4 = pk2(Wr[4], Wr[4]), w5 = pk2(Wr[5], Wr[5]);
            u64t w6 = pk2(Wr[6], Wr[6]), w7 = pk2(Wr[7], Wr[7]), w8 = pk2(Wr[8], Wr[8]);
            u64t bb0 = pk2(bl0, bl0), bb1 = pk2(bl1, bl1), bb2 = pk2(bl2, bl2);
#pragma unroll 1
            for (int it = 0; it < 10; it++) {
                int pi = it * NT + tid;
                if (pi < 10000) {
                    int i0 = pi * 2;
                    float4 hA = __ldg(&g_h4[i0]);
                    float4 hB = __ldg(&g_h4[i0 + 1]);
                    u64t hx = pk2(hA.x, hB.x), hy = pk2(hA.y, hB.y), hz = pk2(hA.z, hB.z);
                    u64t c0 = fma2(hx, w0, fma2(hy, w3, fma2(hz, w6, bb0)));
                    u64t c1 = fma2(hx, w1, fma2(hy, w4, fma2(hz, w7, bb1)));
                    u64t c2 = fma2(hx, w2, fma2(hy, w5, fma2(hz, w8, bb2)));
                    float2 f0 = upk2(c0), f1 = upk2(c1), f2 = upk2(c2);
                    unsigned uA, uB; float eA, kA0, kA1, kA2, eB, kB0, kB1, kB2;
                    node_tail(fmaxf(f0.x,0.f), fmaxf(f1.x,0.f), fmaxf(f2.x,0.f),
                              wo0, wo1, wo2, pb, gW0, gW1, gW2, uA, eA, kA0, kA1, kA2);
                    node_tail(fmaxf(f0.y,0.f), fmaxf(f1.y,0.f), fmaxf(f2.y,0.f),
                              wo0, wo1, wo2, pb, gW0, gW1, gW2, uB, eB, kB0, kB1, kB2);
                    ((uint2*)ukey)[pi] = make_uint2(uA, uB);
                    mymin = min(mymin, min(uA, uB));
                    mymax = max(mymax, max(uA, uB));
                    ssum += eA + eB;
                    a0 = fmaf(eA, kA0, fmaf(eB, kB0, a0));
                    a1 = fmaf(eA, kA1, fmaf(eB, kB1, a1));
                    a2 = fmaf(eA, kA2, fmaf(eB, kB2, a2));
                }
            }
        }
        __syncthreads();

        // ---- phase 4: member fixup over compact list; cache contributions ----
        {
            int tot = (int)s_tot;
            for (int idx = tid; idx < tot; idx += NT) {
                int d = klist[idx];
                float4 mm = mv[idx];
                float4 hv = g_h4[d];
                unsigned uo; float eo, o0, o1, o2;
                node_val(hv, 0.f, 0.f, 0.f, 0.f, Wl, Wr, bl0, bl1, bl2,
                         wo0, wo1, wo2, pb, gW0, gW1, gW2, uo, eo, o0, o1, o2);
                unsigned un; float en, n0, n1, n2;
                node_val(hv, mm.x, mm.y, mm.z, mm.w, Wl, Wr, bl0, bl1, bl2,
                         wo0, wo1, wo2, pb, gW0, gW1, gW2, un, en, n0, n1, n2);
                ukey[d] = un;
                mymin = min(mymin, un); mymax = max(mymax, un);
                ssum += en - eo;
                float c1 = en*n0, c2 = en*n1, c3 = en*n2;
                a0 += c1 - eo*o0; a1 += c2 - eo*o1; a2 += c3 - eo*o2;
                mv[idx] = make_float4(en, c1, c2, c3);   // cached contribution
            }
        }

        // ---- block min/max reduce ----
        mymin = __reduce_min_sync(0xffffffffu, mymin);
        mymax = __reduce_max_sync(0xffffffffu, mymax);
        if (lane == 0) { s_wa[wid] = mymin; s_wb[wid] = mymax; }
        __syncthreads();
        if (wid == 0) {
            unsigned mn = __reduce_min_sync(0xffffffffu, s_wa[lane]);
            unsigned mx = __reduce_max_sync(0xffffffffu, s_wb[lane]);
            if (lane == 0) { s_wa[0] = mn; s_wb[0] = mx; }
        }
        __syncthreads();
        unsigned lo = s_wa[0], hi = s_wb[0];
        __syncthreads();

        // ---- phase 5: adaptive radix select (uint4-vectorized scans) ----
        unsigned rem = KKEEP, ceq = NN;
        while (lo < hi) {
            unsigned width = hi - lo;
            int bits = 32 - __clz(width);
            int shift = bits > 13 ? bits - 13 : 0;
            uint4 zz = make_uint4(0, 0, 0, 0);
            ((uint4*)hist)[tid]        = zz;
            ((uint4*)hist)[NT + tid]   = zz;
            ((uint4*)hist)[2*NT + tid] = zz;
            ((uint4*)hist)[3*NT + tid] = zz;
            __syncthreads();
            unsigned* myh = hist + ((wid & 1) ? NB : 0);
#pragma unroll 1
            for (int it = 0; it < 5; it++) {
                int v4 = it * NT + tid;
                uint4 uu = make_uint4(0,0,0,0);
                bool ok = (v4 < 5000);
                if (ok) uu = ((uint4*)ukey)[v4];
                unsigned bn[4];
                bn[0] = (ok && uu.x >= lo && uu.x <= hi) ? ((uu.x - lo) >> shift) : 0xffffffffu;
                bn[1] = (ok && uu.y >= lo && uu.y <= hi) ? ((uu.y - lo) >> shift) : 0xffffffffu;
                bn[2] = (ok && uu.z >= lo && uu.z <= hi) ? ((uu.z - lo) >> shift) : 0xffffffffu;
                bn[3] = (ok && uu.w >= lo && uu.w <= hi) ? ((uu.w - lo) >> shift) : 0xffffffffu;
#pragma unroll
                for (int j = 0; j < 4; j++) {
                    unsigned msk = __match_any_sync(0xffffffffu, bn[j]);
                    if (bn[j] != 0xffffffffu && (__ffs(msk) - 1) == lane)
                        atomicAdd(&myh[bn[j]], __popc(msk));
                }
            }
            __syncthreads();
            uint4 c0a = ((uint4*)hist)[tid*2], c0b = ((uint4*)hist)[tid*2+1];
            uint4 c1a = ((uint4*)(hist + NB))[tid*2], c1b = ((uint4*)(hist + NB))[tid*2+1];
            unsigned bt[8] = { c0a.x+c1a.x, c0a.y+c1a.y, c0a.z+c1a.z, c0a.w+c1a.w,
                               c0b.x+c1b.x, c0b.y+c1b.y, c0b.z+c1b.z, c0b.w+c1b.w };
            unsigned psum = bt[0]+bt[1]+bt[2]+bt[3]+bt[4]+bt[5]+bt[6]+bt[7];
            unsigned v = psum;
#pragma unroll
            for (int d = 1; d < 32; d <<= 1) { unsigned t = __shfl_down_sync(~0u, v, d); if (lane + d < 32) v += t; }
            if (lane == 0) s_wa[wid] = v;
            __syncthreads();
            if (wid == 0) {
                unsigned x = s_wa[lane];
#pragma unroll
                for (int d = 1; d < 32; d <<= 1) { unsigned t = __shfl_down_sync(~0u, x, d); if (lane + d < 32) x += t; }
                s_wb[lane] = x;
            }
            __syncthreads();
            unsigned c = ((wid < 31) ? s_wb[wid + 1] : 0u) + (v - psum);
#pragma unroll
            for (int q = 7; q >= 0; q--) {
                unsigned hc = bt[q];
                if (c < rem && c + hc >= rem) { s_bin = tid*8 + q; s_cnt = hc; s_rem = rem - c; }
                c += hc;
            }
            __syncthreads();
            unsigned bin = s_bin; rem = s_rem; ceq = s_cnt;
            unsigned nlo = lo + (bin << shift);
            unsigned long long nh = (unsigned long long)nlo + ((shift > 0) ? ((1ull << shift) - 1ull) : 0ull);
            hi = (nh > (unsigned long long)hi) ? hi : (unsigned)nh;
            lo = nlo;
            __syncthreads();
        }
        const unsigned Tu = lo;
        unsigned Itie = NN;

        // ---- phase 6: tie-break (vectorized) ----
        if (rem < ceq) {
            hist[tid] = 0; hist[NB + tid] = 0;
            __syncthreads();
            unsigned* myh = hist + ((wid & 1) ? NB : 0);
#pragma unroll 1
            for (int it = 0; it < 5; it++) {
                int v4 = it * NT + tid;
                uint4 uu = make_uint4(0,0,0,0);
                bool ok = (v4 < 5000);
                if (ok) uu = ((uint4*)ukey)[v4];
                int ib = v4 * 4;
                unsigned bn[4];
                bn[0] = (ok && uu.x == Tu) ? ((unsigned)(ib)     >> 5) : 0xffffffffu;
                bn[1] = (ok && uu.y == Tu) ? ((unsigned)(ib + 1) >> 5) : 0xffffffffu;
                bn[2] = (ok && uu.z == Tu) ? ((unsigned)(ib + 2) >> 5) : 0xffffffffu;
                bn[3] = (ok && uu.w == Tu) ? ((unsigned)(ib + 3) >> 5) : 0xffffffffu;
#pragma unroll
                for (int j = 0; j < 4; j++) {
                    unsigned msk = __match_any_sync(0xffffffffu, bn[j]);
                    if (bn[j] != 0xffffffffu && (__ffs(msk) - 1) == lane)
                        atomicAdd(&myh[bn[j]], __popc(msk));
                }
            }
            __syncthreads();
            unsigned psum = (tid < 625) ? (hist[tid] + hist[NB + tid]) : 0u;
            unsigned v = psum;
#pragma unroll
            for (int d = 1; d < 32; d <<= 1) { unsigned t = __shfl_up_sync(~0u, v, d); if (lane >= d) v += t; }
            if (lane == 31) s_wa[wid] = v;
            __syncthreads();
            if (wid == 0) {
                unsigned x = s_wa[lane];
#pragma unroll
                for (int d = 1; d < 32; d <<= 1) { unsigned t = __shfl_up_sync(~0u, x, d); if (lane >= d) x += t; }
                s_wb[lane] = x;
            }
            __syncthreads();
            unsigned below = (v - psum) + ((wid > 0) ? s_wb[wid - 1] : 0u);
            if (tid < 625 && below < rem && below + psum >= rem) { s_bin = tid; s_rem = rem - below; }
            __syncthreads();
            int bA = (int)s_bin; unsigned r2 = s_rem;
            if (wid == 0) {
                int i = bA * 32 + lane;
                bool f = (i < NN) && (ukey[i] == Tu);
                unsigned m = __ballot_sync(0xffffffffu, f);
                unsigned rk = __popc(m & ((1u << lane) - 1u)) + 1u;
                if (f && rk == r2) s_itie = (unsigned)i;
            }
            __syncthreads();
            Itie = s_itie;
        }

        // ---- phase 7: compact dropped nodes (vectorized reads) ----
        if (tid == 0) s_dn = 0;
        __syncthreads();
        int* dl = (int*)hist;
#pragma unroll 1
        for (int it = 0; it < 5; it++) {
            int v4 = it * NT + tid;
            uint4 uu = make_uint4(0,0,0,0);
            bool ok = (v4 < 5000);
            if (ok) uu = ((uint4*)ukey)[v4];
            int ib = v4 * 4;
#pragma unroll
            for (int j = 0; j < 4; j++) {
                unsigned u = (j == 0) ? uu.x : (j == 1) ? uu.y : (j == 2) ? uu.z : uu.w;
                int i = ib + j;
                bool dr = ok && !((u > Tu) || (u == Tu && (unsigned)i <= Itie));
                unsigned m = __ballot_sync(0xffffffffu, dr);
                if (m) {
                    int leader = __ffs(m) - 1;
                    unsigned base = 0;
                    if (lane == leader) base = atomicAdd(&s_dn, __popc(m));
                    base = __shfl_sync(0xffffffffu, base, leader);
                    if (dr) dl[base + __popc(m & ((1u << lane) - 1u))] = i;
                }
            }
        }
        __syncthreads();

        // ---- phase 8: subtract dropped contributions ----
        {
            int D = (int)s_dn;
            for (int k = tid; k < D; k += NT) {
                int i = dl[k];
                // member? hash lookup
                unsigned slot = ((unsigned)i * 2654435761u) >> 20;
                int want = i + 1;
                int sl = -1;
                for (;;) {
                    int k2 = keysh[slot];
                    if (k2 == want) { sl = (int)slot; break; }
                    if (k2 == 0) break;
                    slot = (slot + 1) & HM;
                }
                if (sl >= 0) {
                    float4 c = mv[val[sl]];    // cached contribution from phase 4
                    ssum -= c.x; a0 -= c.y; a1 -= c.z; a2 -= c.w;
                } else {
                    float4 hv = g_h4[i];
                    unsigned uu; float e, k0, k1, k2v;
                    node_val(hv, 0.f, 0.f, 0.f, 0.f, Wl, Wr, bl0, bl1, bl2,
                             wo0, wo1, wo2, pb, gW0, gW1, gW2, uu, e, k0, k1, k2v);
                    ssum -= e;
                    a0 -= e * k0; a1 -= e * k1; a2 -= e * k2v;
                }
            }
        }

        // ---- phase 9: final reduction + output ----
#pragma unroll
        for (int off = 16; off > 0; off >>= 1) {
            ssum += __shfl_down_sync(0xffffffffu, ssum, off);
            a0   += __shfl_down_sync(0xffffffffu, a0, off);
            a1   += __shfl_down_sync(0xffffffffu, a1, off);
            a2   += __shfl_down_sync(0xffffffffu, a2, off);
        }
        if (lane == 0) { fred[wid] = ssum; fred[32+wid] = a0; fred[64+wid] = a1; fred[96+wid] = a2; }
        __syncthreads();
        if (tid == 0) {
            float S = 0.f, A0 = 0.f, A1 = 0.f, A2 = 0.f;
#pragma unroll
            for (int q = 0; q < 32; q++) { S += fred[q]; A0 += fred[32+q]; A1 += fred[64+q]; A2 += fred[96+q]; }
            float inv = 1.f / S;
            float v0 = fmaxf(A0 * inv, 0.f);
            float v1 = fmaxf(A1 * inv, 0.f);
            float v2 = fmaxf(A2 * inv, 0.f);
            float rr = fmaxf(v0 * __ldg(linW) + v1 * __ldg(linW+1) + v2 * __ldg(linW+2) + __ldg(linb), 0.f);
            g_pathC[p] = rr * __ldg(mlpW + p);
        }
        __syncthreads();
    }
}

__global__ void k_out(const float* __restrict__ mlpb, float* __restrict__ out) {
    __shared__ float sbuf[256];
    int tid = threadIdx.x;
    float v = 0.f;
    for (int i = tid; i < PP; i += 256) v += g_pathC[i];
    sbuf[tid] = v;
    __syncthreads();
    for (int s = 128; s > 0; s >>= 1) { if (tid < s) sbuf[tid] += sbuf[tid + s]; __syncthreads(); }
    if (tid == 0) out[0] = 1.f / (1.f + expf(-(sbuf[0] + mlpb[0])));
}

// ---------------- launch ----------------
extern "C" void kernel_launch(void* const* d_in, const int* in_sizes, int n_in,
                              void* d_out, int out_size) {
    const float* x          = (const float*)d_in[0];
    const int*   edge_index = (const int*)  d_in[1];
    const int*   path_edges = (const int*)  d_in[2];
    const float* W_pool     = (const float*)d_in[3];
    const float* b_pool     = (const float*)d_in[4];
    const float* W_self     = (const float*)d_in[5];
    const float* W_neigh    = (const float*)d_in[6];
    const float* b_conv     = (const float*)d_in[7];
    const float* sub_Wl     = (const float*)d_in[8];
    const float* sub_bl     = (const float*)d_in[9];
    const float* sub_Wr     = (const float*)d_in[10];
    const float* pool_Wrel  = (const float*)d_in[11];
    const float* pool_Wroot = (const float*)d_in[12];
    const float* pool_b     = (const float*)d_in[13];
    const float* gate_W     = (const float*)d_in[14];
    const float* gate_b     = (const float*)d_in[15];
    const float* lin_W      = (const float*)d_in[16];
    const float* lin_b      = (const float*)d_in[17];
    const float* mlp_W      = (const float*)d_in[18];
    const float* mlp_b      = (const float*)d_in[19];
    float* out = (float*)d_out;
    (void)gate_b;

    cudaFuncSetAttribute(k_path, cudaFuncAttributeMaxDynamicSharedMemorySize, SMEM_BYTES);

    k_hp     <<<(NN + 255) / 256, 256>>>(x, W_pool, b_pool);
    k_segmax <<<(EE + 511) / 512, 512>>>(edge_index);
    k_h      <<<(NN + 255) / 256, 256>>>(x, W_self, W_neigh, b_conv);
    k_path   <<<GRID, NT, SMEM_BYTES>>>(path_edges, sub_Wl, sub_bl, sub_Wr,
                                        pool_Wrel, pool_Wroot, pool_b,
                                        gate_W, gate_b, lin_W, lin_b, mlp_W);
    k_out    <<<1, 256>>>(mlp_b, out);
}

// round 10
// speedup vs baseline: 1.0677x; 1.0677x over previous
#include <cuda_runtime.h>
#include <stdint.h>

#define NN    20000
#define EE    200000
#define PP    300
#define EPE   2000
#define KKEEP 16000
#define HS    4096
#define HM    4095
#define NBINS 4096      // bins per histogram copy (4 copies)
#define NT    1024
#define NITER 20        // ceil(NN/NT)
#define GRID  296

// dynamic smem layout (bytes):
//   ukey : 20000 u32        [0,      80000)
//   keysh: 4096  int        [80000,  96384)
//   val  : 4096  int        [96384, 112768)
//   mv   : 2048  float4     [112768,145536)
//   hist : 4*4096 u32       [145536,211072)   (also klist / dl scratch)
#define SMEM_BYTES 211072

__device__ float4 g_h4[NN];
__device__ float  g_hp[NN * 3];
__device__ float  g_agg[NN * 3];
__device__ float  g_pathC[PP];

__device__ __forceinline__ unsigned fkey(float f) {
    unsigned u = __float_as_uint(f);
    return (u & 0x80000000u) ? ~u : (u | 0x80000000u);
}

// MUFU-free fast paths (explicit fmaf chains -> bit-identical across call sites)
__device__ __forceinline__ float tanh_fast(float x) {
    float a = fabsf(x);
    if (a < 0.53f) {
        float x2 = x * x;
        float p = fmaf(x2, -5.3968254e-2f, 1.3333333e-1f);
        p = fmaf(x2, p, -3.3333333e-1f);
        p = fmaf(x2, p, 1.0f);
        return x * p;
    }
    return tanhf(x);
}
__device__ __forceinline__ float exp_fast(float t) {
    if (fabsf(t) < 0.3f) {
        float p = fmaf(t, 4.1666668e-2f, 1.6666667e-1f);
        p = fmaf(t, p, 0.5f);
        p = fmaf(t, p, 1.0f);
        p = fmaf(t, p, 1.0f);
        return p;
    }
    return __expf(t);
}

__device__ __forceinline__ void node_val(
    float4 hv, float m0, float m1, float m2, float ar,
    const float* Wl, const float* Wr,
    float bl0, float bl1, float bl2,
    float wo0, float wo1, float wo2, float pb,
    float gW0, float gW1, float gW2,
    unsigned& u, float& e, float& k0, float& k1, float& k2)
{
    float t0 = fmaf(hv.x, Wr[0], fmaf(hv.y, Wr[3], fmaf(hv.z, Wr[6], bl0)));
    float t1 = fmaf(hv.x, Wr[1], fmaf(hv.y, Wr[4], fmaf(hv.z, Wr[7], bl1)));
    float t2 = fmaf(hv.x, Wr[2], fmaf(hv.y, Wr[5], fmaf(hv.z, Wr[8], bl2)));
    float xc0 = fmaxf(fmaf(m0, Wl[0], fmaf(m1, Wl[3], fmaf(m2, Wl[6], t0))), 0.f);
    float xc1 = fmaxf(fmaf(m0, Wl[1], fmaf(m1, Wl[4], fmaf(m2, Wl[7], t1))), 0.f);
    float xc2 = fmaxf(fmaf(m0, Wl[2], fmaf(m1, Wl[5], fmaf(m2, Wl[8], t2))), 0.f);
    float sc = fmaf(xc0, wo0, fmaf(xc1, wo1, fmaf(xc2, wo2, pb + ar)));
    u = fkey(sc);
    float tv = tanh_fast(sc);
    k0 = xc0 * tv; k1 = xc1 * tv; k2 = xc2 * tv;
    float l = fmaf(k0, gW0, fmaf(k1, gW1, k2 * gW2));   // gb dropped: cancels in softmax
    e = exp_fast(l);
}

// ---------------- global stage ----------------
__global__ void k_hp(const float* __restrict__ x, const float* __restrict__ Wp,
                     const float* __restrict__ bp) {
    int i = blockIdx.x * blockDim.x + threadIdx.x;
    if (i >= NN) return;
    float x0 = x[3*i], x1 = x[3*i+1], x2 = x[3*i+2];
#pragma unroll
    for (int c = 0; c < 3; c++) {
        float v = fmaxf(bp[c] + x0*Wp[c] + x1*Wp[3+c] + x2*Wp[6+c], 0.f);
        g_hp[3*i+c] = v;
        g_agg[3*i+c] = v;
    }
}

__global__ void k_segmax(const int* __restrict__ ei) {
    int e = blockIdx.x * blockDim.x + threadIdx.x;
    if (e >= EE) return;
    int s = ei[e], d = ei[EE + e];
#pragma unroll
    for (int c = 0; c < 3; c++)
        atomicMax((int*)&g_agg[3*d+c], __float_as_int(g_hp[3*s+c]));
}

__global__ void k_h(const float* __restrict__ x, const float* __restrict__ Ws,
                    const float* __restrict__ Wn, const float* __restrict__ bc) {
    int i = blockIdx.x * blockDim.x + threadIdx.x;
    if (i >= NN) return;
    float x0 = x[3*i], x1 = x[3*i+1], x2 = x[3*i+2];
    float a0 = g_agg[3*i], a1 = g_agg[3*i+1], a2 = g_agg[3*i+2];
    float4 o;
    o.x = tanhf(bc[0] + x0*Ws[0] + x1*Ws[3] + x2*Ws[6] + a0*Wn[0] + a1*Wn[3] + a2*Wn[6]);
    o.y = tanhf(bc[1] + x0*Ws[1] + x1*Ws[4] + x2*Ws[7] + a0*Wn[1] + a1*Wn[4] + a2*Wn[7]);
    o.z = tanhf(bc[2] + x0*Ws[2] + x1*Ws[5] + x2*Ws[8] + a0*Wn[2] + a1*Wn[5] + a2*Wn[8]);
    o.w = 0.f;
    g_h4[i] = o;
}

// ---------------- fully fused per-pathway kernel ----------------
__global__ void __launch_bounds__(NT, 1) k_path(
    const int*   __restrict__ pe,
    const float* __restrict__ subWl, const float* __restrict__ subbl,
    const float* __restrict__ subWr,
    const float* __restrict__ pWrel, const float* __restrict__ pWroot,
    const float* __restrict__ poolb,
    const float* __restrict__ gateW, const float* __restrict__ gateb,
    const float* __restrict__ linW,  const float* __restrict__ linb,
    const float* __restrict__ mlpW)
{
    extern __shared__ char sm[];
    unsigned* ukey  = (unsigned*)(sm);
    int*      keysh = (int*)     (sm + 80000);
    int*      val   = (int*)     (sm + 96384);
    float4*   mv    = (float4*)  (sm + 112768);
    unsigned* hist  = (unsigned*)(sm + 145536);

    __shared__ unsigned s_wa[32], s_wb[32];
    __shared__ unsigned s_bin, s_rem, s_cnt, s_itie, s_dn, s_tot;
    __shared__ float    fred[128];

    const int tid  = threadIdx.x;
    const int lane = tid & 31;
    const int wid  = tid >> 5;

#pragma unroll 1
    for (int rep = 0; rep < 2; rep++) {
        const int p = blockIdx.x + rep * GRID;
        if (p >= PP) break;

        float Wl[9], Wr[9];
#pragma unroll
        for (int q = 0; q < 9; q++) { Wl[q] = __ldg(subWl + 9*p + q); Wr[q] = __ldg(subWr + 9*p + q); }
        const float bl0 = __ldg(subbl+3*p), bl1 = __ldg(subbl+3*p+1), bl2 = __ldg(subbl+3*p+2);
        const float wr0 = __ldg(pWrel+3*p), wr1 = __ldg(pWrel+3*p+1), wr2 = __ldg(pWrel+3*p+2);
        const float wo0 = __ldg(pWroot+3*p), wo1 = __ldg(pWroot+3*p+1), wo2 = __ldg(pWroot+3*p+2);
        const float pb  = __ldg(poolb + p);
        const float gW0 = __ldg(gateW+3*p), gW1 = __ldg(gateW+3*p+1), gW2 = __ldg(gateW+3*p+2);

        // ---- phase 0: init keys + mv ----
        ((int4*)keysh)[tid] = make_int4(0, 0, 0, 0);
        float4 z4 = make_float4(0.f, 0.f, 0.f, 0.f);
        mv[tid] = z4; mv[tid + NT] = z4;
        __syncthreads();

        const int* ps = pe + p * 2 * EPE;
        const int* pd = ps + EPE;
        const int e0 = tid, e1 = tid + NT;
        int slotA = -1, slotB = -1;

        // ---- phase 1a: CAS-insert dst keys ----
        if (e0 < EPE) {
            int d = pd[e0];
            unsigned slot = ((unsigned)d * 2654435761u) >> 20;
            for (;;) {
                int prev = atomicCAS(&keysh[slot], 0, d + 1);
                if (prev == 0 || prev == d + 1) break;
                slot = (slot + 1) & HM;
            }
            slotA = (int)slot;
        }
        if (e1 < EPE) {
            int d = pd[e1];
            unsigned slot = ((unsigned)d * 2654435761u) >> 20;
            for (;;) {
                int prev = atomicCAS(&keysh[slot], 0, d + 1);
                if (prev == 0 || prev == d + 1) break;
                slot = (slot + 1) & HM;
            }
            slotB = (int)slot;
        }
        __syncthreads();

        // ---- phase 1b: deterministic compaction: val[slot] = dense index ----
        {
            int4 kk = ((int4*)keysh)[tid];
            unsigned c = (kk.x != 0) + (kk.y != 0) + (kk.z != 0) + (kk.w != 0);
            unsigned v = c;
#pragma unroll
            for (int d = 1; d < 32; d <<= 1) { unsigned t = __shfl_up_sync(~0u, v, d); if (lane >= d) v += t; }
            if (lane == 31) s_wa[wid] = v;
            __syncthreads();
            if (wid == 0) {
                unsigned x = s_wa[lane];
#pragma unroll
                for (int d = 1; d < 32; d <<= 1) { unsigned t = __shfl_up_sync(~0u, x, d); if (lane >= d) x += t; }
                s_wb[lane] = x;
            }
            __syncthreads();
            unsigned excl = (v - c) + ((wid > 0) ? s_wb[wid - 1] : 0u);
            int b = (int)excl;
            if (kk.x) val[4*tid]   = b++;
            if (kk.y) val[4*tid+1] = b++;
            if (kk.z) val[4*tid+2] = b++;
            if (kk.w) val[4*tid+3] = b++;
            if (tid == NT - 1) s_tot = excl + c;
        }
        __syncthreads();

        // ---- phase 1c: accumulate msum/cnt ----
        float* mvf = (float*)mv;
        int idxA = (slotA >= 0) ? val[slotA] : -1;
        int idxB = (slotB >= 0) ? val[slotB] : -1;
        if (e0 < EPE) {
            float4 hv = g_h4[ps[e0]];
            atomicAdd(&mvf[4*idxA],   hv.x);
            atomicAdd(&mvf[4*idxA+1], hv.y);
            atomicAdd(&mvf[4*idxA+2], hv.z);
            atomicAdd(&mvf[4*idxA+3], 1.f);
        }
        if (e1 < EPE) {
            float4 hv = g_h4[ps[e1]];
            atomicAdd(&mvf[4*idxB],   hv.x);
            atomicAdd(&mvf[4*idxB+1], hv.y);
            atomicAdd(&mvf[4*idxB+2], hv.z);
            atomicAdd(&mvf[4*idxB+3], 1.f);
        }
        __syncthreads();

        // ---- phase 1d: normalize mean, zero arel ----
        {
            int tot = (int)s_tot;
            for (int idx = tid; idx < tot; idx += NT) {
                float4 v = mv[idx];
                float inv = 1.f / v.w;
                mv[idx] = make_float4(v.x * inv, v.y * inv, v.z * inv, 0.f);
            }
        }
        __syncthreads();

        // ---- phase 2: arel[d] += xc(s) . Wrel ----
#pragma unroll
        for (int ee = 0; ee < 2; ee++) {
            int e = (ee == 0) ? e0 : e1;
            int myidx = (ee == 0) ? idxA : idxB;
            if (e < EPE) {
                int s = ps[e];
                float4 hv = g_h4[s];
                float m0 = 0.f, m1 = 0.f, m2 = 0.f;
                unsigned slot = ((unsigned)s * 2654435761u) >> 20;
                int want = s + 1;
                for (;;) {
                    int k2 = keysh[slot];
                    if (k2 == want) { float4 mm = mv[val[slot]]; m0 = mm.x; m1 = mm.y; m2 = mm.z; break; }
                    if (k2 == 0) break;
                    slot = (slot + 1) & HM;
                }
                float xc0 = fmaxf(fmaf(m0, Wl[0], fmaf(m1, Wl[3], fmaf(m2, Wl[6], fmaf(hv.x, Wr[0], fmaf(hv.y, Wr[3], fmaf(hv.z, Wr[6], bl0)))))), 0.f);
                float xc1 = fmaxf(fmaf(m0, Wl[1], fmaf(m1, Wl[4], fmaf(m2, Wl[7], fmaf(hv.x, Wr[1], fmaf(hv.y, Wr[4], fmaf(hv.z, Wr[7], bl1)))))), 0.f);
                float xc2 = fmaxf(fmaf(m0, Wl[2], fmaf(m1, Wl[5], fmaf(m2, Wl[8], fmaf(hv.x, Wr[2], fmaf(hv.y, Wr[5], fmaf(hv.z, Wr[8], bl2)))))), 0.f);
                float vv = fmaf(xc0, wr0, fmaf(xc1, wr1, xc2 * wr2));
                atomicAdd(&mvf[4*myidx+3], vv);
            }
        }
        __syncthreads();

        // ---- phase 3: score all nodes (non-member form), accumulate all-sums ----
        float ssum = 0.f, a0 = 0.f, a1 = 0.f, a2 = 0.f;
        unsigned mymin = 0xffffffffu, mymax = 0u;
        for (int i = tid; i < NN; i += NT) {
            float4 hv = __ldg(&g_h4[i]);
            unsigned u; float e, k0, k1, k2;
            node_val(hv, 0.f, 0.f, 0.f, 0.f, Wl, Wr, bl0, bl1, bl2,
                     wo0, wo1, wo2, pb, gW0, gW1, gW2, u, e, k0, k1, k2);
            ukey[i] = u;
            mymin = min(mymin, u); mymax = max(mymax, u);
            ssum += e;
            a0 = fmaf(e, k0, a0); a1 = fmaf(e, k1, a1); a2 = fmaf(e, k2, a2);
        }
        __syncthreads();

        // ---- phase 4: member fixup ----
        for (int slot = tid; slot < HS; slot += NT) {
            int kk = keysh[slot];
            if (kk != 0) {
                int d = kk - 1;
                float4 mm = mv[val[slot]];
                float4 hv = g_h4[d];
                unsigned uo; float eo, o0, o1, o2;
                node_val(hv, 0.f, 0.f, 0.f, 0.f, Wl, Wr, bl0, bl1, bl2,
                         wo0, wo1, wo2, pb, gW0, gW1, gW2, uo, eo, o0, o1, o2);
                unsigned un; float en, n0, n1, n2;
                node_val(hv, mm.x, mm.y, mm.z, mm.w, Wl, Wr, bl0, bl1, bl2,
                         wo0, wo1, wo2, pb, gW0, gW1, gW2, un, en, n0, n1, n2);
                ukey[d] = un;
                mymin = min(mymin, un); mymax = max(mymax, un);
                ssum += en - eo;
                a0 += en*n0 - eo*o0; a1 += en*n1 - eo*o1; a2 += en*n2 - eo*o2;
            }
        }

        // ---- block min/max reduce ----
        mymin = __reduce_min_sync(0xffffffffu, mymin);
        mymax = __reduce_max_sync(0xffffffffu, mymax);
        if (lane == 0) { s_wa[wid] = mymin; s_wb[wid] = mymax; }
        __syncthreads();
        if (wid == 0) {
            unsigned mn = __reduce_min_sync(0xffffffffu, s_wa[lane]);
            unsigned mx = __reduce_max_sync(0xffffffffu, s_wb[lane]);
            if (lane == 0) { s_wa[0] = mn; s_wb[0] = mx; }
        }
        __syncthreads();
        unsigned lo = s_wa[0], hi = s_wb[0];
        __syncthreads();

        // ---- phase 5: adaptive radix select (12-bit passes, 4 histogram copies) ----
        unsigned rem = KKEEP, ceq = NN;
        while (lo < hi) {
            unsigned width = hi - lo;
            int bits = 32 - __clz(width);
            int shift = bits > 12 ? bits - 12 : 0;
            ((uint4*)hist)[tid]        = make_uint4(0, 0, 0, 0);
            ((uint4*)hist)[NT + tid]   = make_uint4(0, 0, 0, 0);
            ((uint4*)hist)[2*NT + tid] = make_uint4(0, 0, 0, 0);
            ((uint4*)hist)[3*NT + tid] = make_uint4(0, 0, 0, 0);
            __syncthreads();
            unsigned* myh = hist + (wid & 3) * NBINS;
            for (int it = 0; it < NITER; it++) {
                int i = it * NT + tid;
                unsigned bin = 0xffffffffu;
                if (i < NN) {
                    unsigned u = ukey[i];
                    if (u >= lo && u <= hi) bin = (u - lo) >> shift;
                }
                unsigned msk = __match_any_sync(0xffffffffu, bin);
                if (bin != 0xffffffffu && (__ffs(msk) - 1) == lane)
                    atomicAdd(&myh[bin], __popc(msk));
            }
            __syncthreads();
            // per-thread 4 bins (tid*4 .. tid*4+3), summed over 4 copies
            uint4 h0 = ((uint4*)hist)[tid];
            uint4 h1 = ((uint4*)(hist + NBINS))[tid];
            uint4 h2 = ((uint4*)(hist + 2*NBINS))[tid];
            uint4 h3 = ((uint4*)(hist + 3*NBINS))[tid];
            unsigned bt[4] = { h0.x+h1.x+h2.x+h3.x, h0.y+h1.y+h2.y+h3.y,
                               h0.z+h1.z+h2.z+h3.z, h0.w+h1.w+h2.w+h3.w };
            unsigned psum = bt[0]+bt[1]+bt[2]+bt[3];
            unsigned v = psum;
#pragma unroll
            for (int d = 1; d < 32; d <<= 1) { unsigned t = __shfl_down_sync(~0u, v, d); if (lane + d < 32) v += t; }
            if (lane == 0) s_wa[wid] = v;
            __syncthreads();
            if (wid == 0) {
                unsigned x = s_wa[lane];
#pragma unroll
                for (int d = 1; d < 32; d <<= 1) { unsigned t = __shfl_down_sync(~0u, x, d); if (lane + d < 32) x += t; }
                s_wb[lane] = x;
            }
            __syncthreads();
            unsigned c = ((wid < 31) ? s_wb[wid + 1] : 0u) + (v - psum);
#pragma unroll
            for (int q = 3; q >= 0; q--) {
                unsigned hc = bt[q];
                if (c < rem && c + hc >= rem) { s_bin = tid*4 + q; s_cnt = hc; s_rem = rem - c; }
                c += hc;
            }
            __syncthreads();
            unsigned bin = s_bin; rem = s_rem; ceq = s_cnt;
            unsigned nlo = lo + (bin << shift);
            unsigned long long nh = (unsigned long long)nlo + ((shift > 0) ? ((1ull << shift) - 1ull) : 0ull);
            hi = (nh > (unsigned long long)hi) ? hi : (unsigned)nh;
            lo = nlo;
            __syncthreads();
        }
        const unsigned Tu = lo;
        unsigned Itie = NN;

        // ---- phase 6: single-pass index tie-break (625 bins, 4 copies) ----
        if (rem < ceq) {
            hist[tid] = 0; hist[NT + tid] = 0;
            hist[2*NT + tid] = 0; hist[3*NT + tid] = 0;
            __syncthreads();
            unsigned* myh = hist + (wid & 3) * NT;
            for (int it = 0; it < NITER; it++) {
                int i = it * NT + tid;
                unsigned bin = 0xffffffffu;
                if (i < NN && ukey[i] == Tu) bin = (unsigned)i >> 5;
                unsigned msk = __match_any_sync(0xffffffffu, bin);
                if (bin != 0xffffffffu && (__ffs(msk) - 1) == lane)
                    atomicAdd(&myh[bin], __popc(msk));
            }
            __syncthreads();
            unsigned psum = (tid < 625) ? (hist[tid] + hist[NT + tid] + hist[2*NT + tid] + hist[3*NT + tid]) : 0u;
            unsigned v = psum;
#pragma unroll
            for (int d = 1; d < 32; d <<= 1) { unsigned t = __shfl_up_sync(~0u, v, d); if (lane >= d) v += t; }
            if (lane == 31) s_wa[wid] = v;
            __syncthreads();
            if (wid == 0) {
                unsigned x = s_wa[lane];
#pragma unroll
                for (int d = 1; d < 32; d <<= 1) { unsigned t = __shfl_up_sync(~0u, x, d); if (lane >= d) x += t; }
                s_wb[lane] = x;
            }
            __syncthreads();
            unsigned below = (v - psum) + ((wid > 0) ? s_wb[wid - 1] : 0u);
            if (tid < 625 && below < rem && below + psum >= rem) { s_bin = tid; s_rem = rem - below; }
            __syncthreads();
            int bA = (int)s_bin; unsigned r2 = s_rem;
            if (wid == 0) {
                int i = bA * 32 + lane;
                bool f = (i < NN) && (ukey[i] == Tu);
                unsigned m = __ballot_sync(0xffffffffu, f);
                unsigned rk = __popc(m & ((1u << lane) - 1u)) + 1u;
                if (f && rk == r2) s_itie = (unsigned)i;
            }
            __syncthreads();
            Itie = s_itie;
        }

        // ---- phase 7: compact dropped nodes ----
        if (tid == 0) s_dn = 0;
        __syncthreads();
        int* dl = (int*)hist;
        for (int it = 0; it < NITER; it++) {
            int i = it * NT + tid;
            bool dr = false;
            if (i < NN) {
                unsigned u = ukey[i];
                dr = !((u > Tu) || (u == Tu && (unsigned)i <= Itie));
            }
            unsigned m = __ballot_sync(0xffffffffu, dr);
            if (m) {
                int leader = __ffs(m) - 1;
                unsigned base = 0;
                if (lane == leader) base = atomicAdd(&s_dn, __popc(m));
                base = __shfl_sync(0xffffffffu, base, leader);
                if (dr) dl[base + __popc(m & ((1u << lane) - 1u))] = i;
            }
        }
        __syncthreads();

        // ---- phase 8: subtract dropped contributions ----
        {
            int D = (int)s_dn;
            for (int k = tid; k < D; k += NT) {
                int i = dl[k];
                float4 hv = g_h4[i];
                float m0 = 0.f, m1 = 0.f, m2 = 0.f, ar = 0.f;
                unsigned slot = ((unsigned)i * 2654435761u) >> 20;
                int want = i + 1;
                for (;;) {
                    int k2 = keysh[slot];
                    if (k2 == want) { float4 mm = mv[val[slot]]; m0 = mm.x; m1 = mm.y; m2 = mm.z; ar = mm.w; break; }
                    if (k2 == 0) break;
                    slot = (slot + 1) & HM;
                }
                unsigned uu; float e, k0, k1, k2v;
                node_val(hv, m0, m1, m2, ar, Wl, Wr, bl0, bl1, bl2,
                         wo0, wo1, wo2, pb, gW0, gW1, gW2, uu, e, k0, k1, k2v);
                ssum -= e;
                a0 -= e * k0; a1 -= e * k1; a2 -= e * k2v;
            }
        }

        // ---- phase 9: final reduction + output ----
#pragma unroll
        for (int off = 16; off > 0; off >>= 1) {
            ssum += __shfl_down_sync(0xffffffffu, ssum, off);
            a0   += __shfl_down_sync(0xffffffffu, a0, off);
            a1   += __shfl_down_sync(0xffffffffu, a1, off);
            a2   += __shfl_down_sync(0xffffffffu, a2, off);
        }
        if (lane == 0) { fred[wid] = ssum; fred[32+wid] = a0; fred[64+wid] = a1; fred[96+wid] = a2; }
        __syncthreads();
        if (tid == 0) {
            float S = 0.f, A0 = 0.f, A1 = 0.f, A2 = 0.f;
#pragma unroll
            for (int q = 0; q < 32; q++) { S += fred[q]; A0 += fred[32+q]; A1 += fred[64+q]; A2 += fred[96+q]; }
            float inv = 1.f / S;
            float v0 = fmaxf(A0 * inv, 0.f);
            float v1 = fmaxf(A1 * inv, 0.f);
            float v2 = fmaxf(A2 * inv, 0.f);
            float rr = fmaxf(v0 * __ldg(linW) + v1 * __ldg(linW+1) + v2 * __ldg(linW+2) + __ldg(linb), 0.f);
            g_pathC[p] = rr * __ldg(mlpW + p);
        }
        __syncthreads();   // protect smem reuse across reps
    }
}

__global__ void k_out(const float* __restrict__ mlpb, float* __restrict__ out) {
    __shared__ float sbuf[256];
    int tid = threadIdx.x;
    float v = 0.f;
    for (int i = tid; i < PP; i += 256) v += g_pathC[i];
    sbuf[tid] = v;
    __syncthreads();
    for (int s = 128; s > 0; s >>= 1) { if (tid < s) sbuf[tid] += sbuf[tid + s]; __syncthreads(); }
    if (tid == 0) out[0] = 1.f / (1.f + expf(-(sbuf[0] + mlpb[0])));
}

// ---------------- launch ----------------
extern "C" void kernel_launch(void* const* d_in, const int* in_sizes, int n_in,
                              void* d_out, int out_size) {
    const float* x          = (const float*)d_in[0];
    const int*   edge_index = (const int*)  d_in[1];
    const int*   path_edges = (const int*)  d_in[2];
    const float* W_pool     = (const float*)d_in[3];
    const float* b_pool     = (const float*)d_in[4];
    const float* W_self     = (const float*)d_in[5];
    const float* W_neigh    = (const float*)d_in[6];
    const float* b_conv     = (const float*)d_in[7];
    const float* sub_Wl     = (const float*)d_in[8];
    const float* sub_bl     = (const float*)d_in[9];
    const float* sub_Wr     = (const float*)d_in[10];
    const float* pool_Wrel  = (const float*)d_in[11];
    const float* pool_Wroot = (const float*)d_in[12];
    const float* pool_b     = (const float*)d_in[13];
    const float* gate_W     = (const float*)d_in[14];
    const float* gate_b     = (const float*)d_in[15];
    const float* lin_W      = (const float*)d_in[16];
    const float* lin_b      = (const float*)d_in[17];
    const float* mlp_W      = (const float*)d_in[18];
    const float* mlp_b      = (const float*)d_in[19];
    float* out = (float*)d_out;
    (void)gate_b;   // constant gate bias cancels in softmax

    cudaFuncSetAttribute(k_path, cudaFuncAttributeMaxDynamicSharedMemorySize, SMEM_BYTES);

    k_hp     <<<(NN + 255) / 256, 256>>>(x, W_pool, b_pool);
    k_segmax <<<(EE + 511) / 512, 512>>>(edge_index);
    k_h      <<<(NN + 255) / 256, 256>>>(x, W_self, W_neigh, b_conv);
    k_path   <<<GRID, NT, SMEM_BYTES>>>(path_edges, sub_Wl, sub_bl, sub_Wr,
                                        pool_Wrel, pool_Wroot, pool_b,
                                        gate_W, gate_b, lin_W, lin_b, mlp_W);
    k_out    <<<1, 256>>>(mlp_b, out);
}